// round 10
// baseline (speedup 1.0000x reference)
#include <cuda_runtime.h>
#include <cuda_fp16.h>
#include <stdint.h>

// Problem constants
#define T_TOK 2048
#define H_DIM 1024
#define I_DIM 768
#define E_NUM 8
#define K_TOP 2
#define A_TOT (T_TOK * K_TOP)   // 4096

// ---------------------------------------------------------------------------
// Device-global scratch
// ---------------------------------------------------------------------------
__device__ int   g_count[E_NUM];
__device__ int   g_offset[E_NUM];
__device__ int   g_perm[A_TOT];
__device__ __half g_x  [(size_t)T_TOK * H_DIM];
__device__ __half g_wgu[(size_t)E_NUM * 2 * I_DIM * H_DIM];
__device__ __half g_wd [(size_t)E_NUM * H_DIM * I_DIM];
__device__ __half g_act[(size_t)A_TOT * I_DIM];

// ---------------------------------------------------------------------------
// PTX helpers (base PTX, valid on sm_100 target)
// ---------------------------------------------------------------------------
__device__ __forceinline__ uint32_t smem_u32(const void* p) {
    uint32_t a;
    asm("{ .reg .u64 t; cvta.to.shared.u64 t, %1; cvt.u32.u64 %0, t; }" : "=r"(a) : "l"(p));
    return a;
}

#define LDSM_X4(R0, R1, R2, R3, ADDR) \
    asm volatile("ldmatrix.sync.aligned.m8n8.x4.shared.b16 {%0,%1,%2,%3}, [%4];" \
        : "=r"(R0), "=r"(R1), "=r"(R2), "=r"(R3) : "r"(ADDR))

#define MMA_F16(D, A, B0, B1) \
    asm volatile("mma.sync.aligned.m16n8k16.row.col.f32.f16.f16.f32 " \
        "{%0,%1,%2,%3}, {%4,%5,%6,%7}, {%8,%9}, {%0,%1,%2,%3};" \
        : "+f"((D)[0]), "+f"((D)[1]), "+f"((D)[2]), "+f"((D)[3]) \
        : "r"((A)[0]), "r"((A)[1]), "r"((A)[2]), "r"((A)[3]), "r"(B0), "r"(B1))

#define CP_ASYNC16(DST, SRC, SZ) \
    asm volatile("cp.async.cg.shared.global [%0], [%1], 16, %2;" \
        :: "r"(DST), "l"(SRC), "r"(SZ))
#define CP_COMMIT  asm volatile("cp.async.commit_group;" ::: "memory")
#define CP_WAIT2   asm volatile("cp.async.wait_group 2;" ::: "memory")

__device__ __forceinline__ uint32_t pack_h2(__half a, __half b) {
    return (uint32_t)__half_as_ushort(a) | ((uint32_t)__half_as_ushort(b) << 16);
}

// ---------------------------------------------------------------------------
// Fused conversion kernel: fp32 -> fp16 for X, Wgu, Wd
// ---------------------------------------------------------------------------
#define NX4  (T_TOK * H_DIM / 4)
#define NG4  (E_NUM * 2 * I_DIM * H_DIM / 4)
#define ND4  (E_NUM * H_DIM * I_DIM / 4)

__device__ __forceinline__ void conv_seg(const float* __restrict__ src,
                                         __half* __restrict__ dst, int n4,
                                         int start, int stride) {
    for (int i = start; i < n4; i += stride) {
        float4 v = ((const float4*)src)[i];
        uint2 u;
        u.x = pack_h2(__float2half_rn(v.x), __float2half_rn(v.y));
        u.y = pack_h2(__float2half_rn(v.z), __float2half_rn(v.w));
        ((uint2*)dst)[i] = u;
    }
}

__global__ void conv_all(const float* __restrict__ X,
                         const float* __restrict__ Wgu,
                         const float* __restrict__ Wd) {
    int start = blockIdx.x * blockDim.x + threadIdx.x;
    int stride = gridDim.x * blockDim.x;
    conv_seg(Wgu, g_wgu, NG4, start, stride);
    conv_seg(Wd,  g_wd,  ND4, start, stride);
    conv_seg(X,   g_x,   NX4, start, stride);
}

// ---------------------------------------------------------------------------
// Zero the output (poisoned by harness; gemm2 accumulates via atomics)
// ---------------------------------------------------------------------------
__global__ void zero_out(float* __restrict__ out) {
    int i = blockIdx.x * blockDim.x + threadIdx.x;
    int n4 = T_TOK * H_DIM / 4;
    int stride = gridDim.x * blockDim.x;
    for (; i < n4; i += stride)
        ((float4*)out)[i] = make_float4(0.f, 0.f, 0.f, 0.f);
}

// ---------------------------------------------------------------------------
// Routing: single block
// ---------------------------------------------------------------------------
__global__ void route_all(const int* __restrict__ topk) {
    __shared__ int cnt[E_NUM], cur[E_NUM];
    int tid = threadIdx.x;
    if (tid < E_NUM) cnt[tid] = 0;
    __syncthreads();
    for (int a = tid; a < A_TOT; a += blockDim.x) atomicAdd(&cnt[topk[a]], 1);
    __syncthreads();
    if (tid == 0) {
        int s = 0;
        for (int e = 0; e < E_NUM; e++) {
            g_count[e] = cnt[e];
            g_offset[e] = s;
            cur[e] = s;
            s += cnt[e];
        }
    }
    __syncthreads();
    for (int a = tid; a < A_TOT; a += blockDim.x) {
        int e = topk[a];
        int s = atomicAdd(&cur[e], 1);
        g_perm[s] = a;
    }
}

// ---------------------------------------------------------------------------
// SMEM: KC=64 fp16 cols, stride 72 (conflict-free ldmatrix), 3 stages.
// Per stage: A(128x72) | B(128x72) = 36 KB.  3 stages = 108 KB/CTA, 2 CTAs/SM.
// ---------------------------------------------------------------------------
#define KC       64
#define STRIDE   72
#define TILE_E   (128 * STRIDE)       // 9216 elems
#define STAGE_E  (2 * TILE_E)         // 18432
#define NSTAGE   3
#define SMEM_BYTES (NSTAGE * STAGE_E * 2)  // 110592 B

__device__ __forceinline__ void load_afrag(uint32_t sb, int eoff, int row0, int kk,
                                           int lane, uint32_t a[4]) {
    int row = row0 + (lane & 15);
    int col = kk + ((lane >> 4) << 3);
    uint32_t addr = sb + (uint32_t)(eoff + row * STRIDE + col) * 2;
    LDSM_X4(a[0], a[1], a[2], a[3], addr);
}
__device__ __forceinline__ void load_bfrag(uint32_t sb, int eoff, int nbase, int kk,
                                           int lane, uint32_t b[4]) {
    int row = nbase + (((lane >> 4) & 1) << 3) + (lane & 7);
    int col = kk + (((lane >> 3) & 1) << 3);
    uint32_t addr = sb + (uint32_t)(eoff + row * STRIDE + col) * 2;
    LDSM_X4(b[0], b[1], b[2], b[3], addr);
}

// ---------------------------------------------------------------------------
// GEMM1: act = silu(X*Wg^T) * (X*Wu^T).  Block 128 slots x (64 gate + 64 up).
// 256 threads, 8 warps (4M x 2N), 2 CTAs/SM.
// ---------------------------------------------------------------------------
#define NCH1 (H_DIM / KC)   // 16

__global__ __launch_bounds__(256, 2)
void gemm1(void) {
    const int e   = blockIdx.z;
    const int cnt = g_count[e];
    const int m0  = blockIdx.x * 128;
    if (m0 >= cnt) return;
    const int off  = g_offset[e];
    const int n0g  = blockIdx.y * 64;
    const int cntm = cnt - m0;

    extern __shared__ __half smem[];
    __shared__ int rowtok[128];
    const uint32_t sb = smem_u32(smem);

    const int tid = threadIdx.x, lane = tid & 31, wid = tid >> 5;
    const int wm = wid & 3, wn = wid >> 2;

    if (tid < 128)
        rowtok[tid] = (tid < cntm) ? g_perm[off + m0 + tid] / K_TOP : -1;
    __syncthreads();

    const __half* wb = g_wgu + (size_t)e * (2 * I_DIM) * H_DIM;

    auto issue = [&](int c) {
        const int k0 = c * KC;
        const int soE = (c % NSTAGE) * STAGE_E;
        #pragma unroll
        for (int i = 0; i < 8; i++) {
            int idx = tid + i * 256;
            int mat = idx >> 10;             // 0=A 1=B
            int row = (idx >> 3) & 127;
            int seg = idx & 7;
            uint32_t dst = sb + (uint32_t)(soE + mat * TILE_E + row * STRIDE + seg * 8) * 2;
            if (mat == 0) {
                int tok = rowtok[row];
                const __half* src = g_x + (size_t)(tok < 0 ? 0 : tok) * H_DIM + k0 + seg * 8;
                CP_ASYNC16(dst, src, (tok < 0) ? 0u : 16u);
            } else {
                int wr = (row < 64) ? (n0g + row) : (I_DIM + n0g + row - 64);
                const __half* src = wb + (size_t)wr * H_DIM + k0 + seg * 8;
                CP_ASYNC16(dst, src, 16u);
            }
        }
        CP_COMMIT;
    };

    float accG[2][4][4], accU[2][4][4];
    #pragma unroll
    for (int a = 0; a < 2; a++)
        #pragma unroll
        for (int b = 0; b < 4; b++)
            #pragma unroll
            for (int c = 0; c < 4; c++) { accG[a][b][c] = 0.f; accU[a][b][c] = 0.f; }

    issue(0);
    issue(1);

    for (int c = 0; c < NCH1; c++) {
        if (c + 2 < NCH1) issue(c + 2); else CP_COMMIT;   // keep 3 groups outstanding
        CP_WAIT2;                                          // chunk c complete
        __syncthreads();

        const int so = (c % NSTAGE) * STAGE_E;
        #pragma unroll
        for (int kk = 0; kk < KC; kk += 16) {
            uint32_t ah[2][4], bg[2][4], bu[2][4];
            #pragma unroll
            for (int mt = 0; mt < 2; mt++)
                load_afrag(sb, so, wm * 32 + mt * 16, kk, lane, ah[mt]);
            #pragma unroll
            for (int p = 0; p < 2; p++) {
                load_bfrag(sb, so + TILE_E, wn * 32 + p * 16,      kk, lane, bg[p]);
                load_bfrag(sb, so + TILE_E, wn * 32 + p * 16 + 64, kk, lane, bu[p]);
            }
            #pragma unroll
            for (int p = 0; p < 2; p++) {
                #pragma unroll
                for (int mt = 0; mt < 2; mt++) {
                    #pragma unroll
                    for (int q = 0; q < 2; q++) {
                        MMA_F16(accG[mt][2 * p + q], ah[mt], bg[p][2 * q], bg[p][2 * q + 1]);
                        MMA_F16(accU[mt][2 * p + q], ah[mt], bu[p][2 * q], bu[p][2 * q + 1]);
                    }
                }
            }
        }
        __syncthreads();   // protect stage before chunk c+3 overwrites it
    }

    // epilogue: silu(gate)*up -> fp16 act
    const int gid = lane >> 2, tig = lane & 3;
    #pragma unroll
    for (int mt = 0; mt < 2; mt++) {
        #pragma unroll
        for (int nt = 0; nt < 4; nt++) {
            int colg = n0g + wn * 32 + nt * 8 + 2 * tig;
            #pragma unroll
            for (int h = 0; h < 2; h++) {
                int rowl = wm * 32 + mt * 16 + gid + h * 8;
                if (rowl < cntm) {
                    float g0 = accG[mt][nt][2 * h],     u0 = accU[mt][nt][2 * h];
                    float g1 = accG[mt][nt][2 * h + 1], u1 = accU[mt][nt][2 * h + 1];
                    float v0 = (g0 / (1.f + __expf(-g0))) * u0;
                    float v1 = (g1 / (1.f + __expf(-g1))) * u1;
                    size_t o = (size_t)(off + m0 + rowl) * I_DIM + colg;
                    *(uint32_t*)(g_act + o) = pack_h2(__float2half_rn(v0), __float2half_rn(v1));
                }
            }
        }
    }
}

// ---------------------------------------------------------------------------
// GEMM2 + combine: out[t,:] += w * (act * Wd^T).  Block 128 slots x 128 H.
// ---------------------------------------------------------------------------
#define NCH2 (I_DIM / KC)   // 12

__global__ __launch_bounds__(256, 2)
void gemm2(const float* __restrict__ wts, float* __restrict__ out) {
    const int e   = blockIdx.z;
    const int cnt = g_count[e];
    const int m0  = blockIdx.x * 128;
    if (m0 >= cnt) return;
    const int off  = g_offset[e];
    const int n0   = blockIdx.y * 128;
    const int cntm = cnt - m0;

    extern __shared__ __half smem[];
    const uint32_t sb = smem_u32(smem);

    const int tid = threadIdx.x, lane = tid & 31, wid = tid >> 5;
    const int wm = wid & 3, wn = wid >> 2;

    const __half* wb = g_wd + (size_t)e * H_DIM * I_DIM;

    auto issue = [&](int c) {
        const int k0 = c * KC;
        const int soE = (c % NSTAGE) * STAGE_E;
        #pragma unroll
        for (int i = 0; i < 8; i++) {
            int idx = tid + i * 256;
            int mat = idx >> 10;
            int row = (idx >> 3) & 127;
            int seg = idx & 7;
            uint32_t dst = sb + (uint32_t)(soE + mat * TILE_E + row * STRIDE + seg * 8) * 2;
            if (mat == 0) {
                int r = (row < cntm) ? row : 0;
                const __half* src = g_act + (size_t)(off + m0 + r) * I_DIM + k0 + seg * 8;
                CP_ASYNC16(dst, src, (row < cntm) ? 16u : 0u);
            } else {
                const __half* src = wb + (size_t)(n0 + row) * I_DIM + k0 + seg * 8;
                CP_ASYNC16(dst, src, 16u);
            }
        }
        CP_COMMIT;
    };

    float acc[2][8][4];
    #pragma unroll
    for (int a = 0; a < 2; a++)
        #pragma unroll
        for (int b = 0; b < 8; b++)
            #pragma unroll
            for (int c = 0; c < 4; c++) acc[a][b][c] = 0.f;

    issue(0);
    issue(1);

    for (int c = 0; c < NCH2; c++) {
        if (c + 2 < NCH2) issue(c + 2); else CP_COMMIT;
        CP_WAIT2;
        __syncthreads();

        const int so = (c % NSTAGE) * STAGE_E;
        #pragma unroll
        for (int kk = 0; kk < KC; kk += 16) {
            uint32_t ah[2][4], bh[4][4];
            #pragma unroll
            for (int mt = 0; mt < 2; mt++)
                load_afrag(sb, so, wm * 32 + mt * 16, kk, lane, ah[mt]);
            #pragma unroll
            for (int p = 0; p < 4; p++)
                load_bfrag(sb, so + TILE_E, wn * 64 + p * 16, kk, lane, bh[p]);
            #pragma unroll
            for (int p = 0; p < 4; p++) {
                #pragma unroll
                for (int mt = 0; mt < 2; mt++) {
                    #pragma unroll
                    for (int q = 0; q < 2; q++)
                        MMA_F16(acc[mt][2 * p + q], ah[mt], bh[p][2 * q], bh[p][2 * q + 1]);
                }
            }
        }
        __syncthreads();
    }

    // fused combine epilogue: out[t, col] += w * acc  via vector atomics
    const int gid = lane >> 2, tig = lane & 3;
    #pragma unroll
    for (int mt = 0; mt < 2; mt++) {
        #pragma unroll
        for (int h = 0; h < 2; h++) {
            int rowl = wm * 32 + mt * 16 + gid + h * 8;
            if (rowl < cntm) {
                int a = g_perm[off + m0 + rowl];
                int t = a / K_TOP;
                float w = wts[a];
                float* obase = out + (size_t)t * H_DIM;
                #pragma unroll
                for (int nt = 0; nt < 8; nt++) {
                    int col = n0 + wn * 64 + nt * 8 + 2 * tig;
                    float2 r = make_float2(w * acc[mt][nt][2 * h],
                                           w * acc[mt][nt][2 * h + 1]);
                    atomicAdd((float2*)(obase + col), r);
                }
            }
        }
    }
}

// ---------------------------------------------------------------------------
// Launch
// ---------------------------------------------------------------------------
extern "C" void kernel_launch(void* const* d_in, const int* in_sizes, int n_in,
                              void* d_out, int out_size) {
    const float* X    = (const float*)d_in[0];
    const float* Wgu  = (const float*)d_in[1];
    const float* Wd   = (const float*)d_in[2];
    const int*   topk = (const int*)  d_in[3];
    const float* wts  = (const float*)d_in[4];
    float*       out  = (float*)d_out;

    cudaFuncSetAttribute(gemm1, cudaFuncAttributeMaxDynamicSharedMemorySize, SMEM_BYTES);
    cudaFuncSetAttribute(gemm2, cudaFuncAttributeMaxDynamicSharedMemorySize, SMEM_BYTES);

    route_all<<<1, 1024>>>(topk);
    conv_all<<<1184, 256>>>(X, Wgu, Wd);
    zero_out<<<512, 256>>>(out);

    dim3 g1(A_TOT / 128, I_DIM / 64, E_NUM);    // (32, 12, 8)
    gemm1<<<g1, 256, SMEM_BYTES>>>();

    dim3 g2(A_TOT / 128, H_DIM / 128, E_NUM);   // (32, 8, 8)
    gemm2<<<g2, 256, SMEM_BYTES>>>(wts, out);
}

// round 11
// speedup vs baseline: 1.0527x; 1.0527x over previous
#include <cuda_runtime.h>
#include <cuda_fp16.h>
#include <stdint.h>

// Problem constants
#define T_TOK 2048
#define H_DIM 1024
#define I_DIM 768
#define E_NUM 8
#define K_TOP 2
#define A_TOT (T_TOK * K_TOP)   // 4096

// ---------------------------------------------------------------------------
// Device-global scratch
// ---------------------------------------------------------------------------
__device__ int   g_count[E_NUM];
__device__ int   g_offset[E_NUM];
__device__ int   g_perm[A_TOT];
__device__ __half g_x  [(size_t)T_TOK * H_DIM];
__device__ __half g_wgu[(size_t)E_NUM * 2 * I_DIM * H_DIM];
__device__ __half g_wd [(size_t)E_NUM * H_DIM * I_DIM];
__device__ __half g_act[(size_t)A_TOT * I_DIM];

// ---------------------------------------------------------------------------
// PTX helpers (base PTX, valid on sm_100 target)
// ---------------------------------------------------------------------------
__device__ __forceinline__ uint32_t smem_u32(const void* p) {
    uint32_t a;
    asm("{ .reg .u64 t; cvta.to.shared.u64 t, %1; cvt.u32.u64 %0, t; }" : "=r"(a) : "l"(p));
    return a;
}

#define LDSM_X4(R0, R1, R2, R3, ADDR) \
    asm volatile("ldmatrix.sync.aligned.m8n8.x4.shared.b16 {%0,%1,%2,%3}, [%4];" \
        : "=r"(R0), "=r"(R1), "=r"(R2), "=r"(R3) : "r"(ADDR))

#define MMA_F16(D, A, B0, B1) \
    asm volatile("mma.sync.aligned.m16n8k16.row.col.f32.f16.f16.f32 " \
        "{%0,%1,%2,%3}, {%4,%5,%6,%7}, {%8,%9}, {%0,%1,%2,%3};" \
        : "+f"((D)[0]), "+f"((D)[1]), "+f"((D)[2]), "+f"((D)[3]) \
        : "r"((A)[0]), "r"((A)[1]), "r"((A)[2]), "r"((A)[3]), "r"(B0), "r"(B1))

#define CP_ASYNC16(DST, SRC, SZ) \
    asm volatile("cp.async.cg.shared.global [%0], [%1], 16, %2;" \
        :: "r"(DST), "l"(SRC), "r"(SZ))
#define CP_COMMIT  asm volatile("cp.async.commit_group;" ::: "memory")
#define CP_WAIT1   asm volatile("cp.async.wait_group 1;" ::: "memory")
#define CP_WAIT0   asm volatile("cp.async.wait_group 0;" ::: "memory")

__device__ __forceinline__ uint32_t pack_h2(__half a, __half b) {
    return (uint32_t)__half_as_ushort(a) | ((uint32_t)__half_as_ushort(b) << 16);
}

// ---------------------------------------------------------------------------
// Fused conversion + output-zero kernel.  Grid fixed at 1024 x 256 = 262144
// threads so every segment has an exact trip count (no bounds checks):
//   Wgu: 3145728 float4 -> 12 iters;  Wd: 1572864 -> 6;  X: 524288 -> 2;
//   out zero: 524288 float4 -> 2.
// Unrolled independent iterations give MLP >= 6 per thread.
// ---------------------------------------------------------------------------
#define CVT_THREADS 262144
#define NG4  (E_NUM * 2 * I_DIM * H_DIM / 4)   // 3145728
#define ND4  (E_NUM * H_DIM * I_DIM / 4)       // 1572864
#define NX4  (T_TOK * H_DIM / 4)               // 524288

__global__ void conv_all(const float* __restrict__ X,
                         const float* __restrict__ Wgu,
                         const float* __restrict__ Wd,
                         float* __restrict__ out) {
    const int t = blockIdx.x * blockDim.x + threadIdx.x;

    // Wgu: 12 iterations
    #pragma unroll
    for (int j = 0; j < 12; j++) {
        int i = t + j * CVT_THREADS;
        float4 v = ((const float4*)Wgu)[i];
        uint2 u;
        u.x = pack_h2(__float2half_rn(v.x), __float2half_rn(v.y));
        u.y = pack_h2(__float2half_rn(v.z), __float2half_rn(v.w));
        ((uint2*)g_wgu)[i] = u;
    }
    // Wd: 6 iterations
    #pragma unroll
    for (int j = 0; j < 6; j++) {
        int i = t + j * CVT_THREADS;
        float4 v = ((const float4*)Wd)[i];
        uint2 u;
        u.x = pack_h2(__float2half_rn(v.x), __float2half_rn(v.y));
        u.y = pack_h2(__float2half_rn(v.z), __float2half_rn(v.w));
        ((uint2*)g_wd)[i] = u;
    }
    // X: 2 iterations
    #pragma unroll
    for (int j = 0; j < 2; j++) {
        int i = t + j * CVT_THREADS;
        float4 v = ((const float4*)X)[i];
        uint2 u;
        u.x = pack_h2(__float2half_rn(v.x), __float2half_rn(v.y));
        u.y = pack_h2(__float2half_rn(v.z), __float2half_rn(v.w));
        ((uint2*)g_x)[i] = u;
    }
    // zero out (harness poisons it; gemm2 accumulates atomically)
    #pragma unroll
    for (int j = 0; j < 2; j++) {
        int i = t + j * CVT_THREADS;
        ((float4*)out)[i] = make_float4(0.f, 0.f, 0.f, 0.f);
    }
}

// ---------------------------------------------------------------------------
// Routing: single block
// ---------------------------------------------------------------------------
__global__ void route_all(const int* __restrict__ topk) {
    __shared__ int cnt[E_NUM], cur[E_NUM];
    int tid = threadIdx.x;
    if (tid < E_NUM) cnt[tid] = 0;
    __syncthreads();
    for (int a = tid; a < A_TOT; a += blockDim.x) atomicAdd(&cnt[topk[a]], 1);
    __syncthreads();
    if (tid == 0) {
        int s = 0;
        for (int e = 0; e < E_NUM; e++) {
            g_count[e] = cnt[e];
            g_offset[e] = s;
            cur[e] = s;
            s += cnt[e];
        }
    }
    __syncthreads();
    for (int a = tid; a < A_TOT; a += blockDim.x) {
        int e = topk[a];
        int s = atomicAdd(&cur[e], 1);
        g_perm[s] = a;
    }
}

// ---------------------------------------------------------------------------
// SMEM: KC=64 fp16 cols, stride 72 (conflict-free ldmatrix), 2 stages.
// Per stage: A(128x72) | B(128x72) = 36 KB.  2 stages = 72 KB/CTA, 2 CTAs/SM.
// ---------------------------------------------------------------------------
#define KC       64
#define STRIDE   72
#define TILE_E   (128 * STRIDE)       // 9216 elems
#define STAGE_E  (2 * TILE_E)         // 18432
#define SMEM_BYTES (2 * STAGE_E * 2)  // 73728 B

__device__ __forceinline__ void load_afrag(uint32_t sb, int eoff, int row0, int kk,
                                           int lane, uint32_t a[4]) {
    int row = row0 + (lane & 15);
    int col = kk + ((lane >> 4) << 3);
    uint32_t addr = sb + (uint32_t)(eoff + row * STRIDE + col) * 2;
    LDSM_X4(a[0], a[1], a[2], a[3], addr);
}
__device__ __forceinline__ void load_bfrag(uint32_t sb, int eoff, int nbase, int kk,
                                           int lane, uint32_t b[4]) {
    int row = nbase + (((lane >> 4) & 1) << 3) + (lane & 7);
    int col = kk + (((lane >> 3) & 1) << 3);
    uint32_t addr = sb + (uint32_t)(eoff + row * STRIDE + col) * 2;
    LDSM_X4(b[0], b[1], b[2], b[3], addr);
}

// ---------------------------------------------------------------------------
// GEMM1: act = silu(X*Wg^T) * (X*Wu^T).  Block 128 slots x (64 gate + 64 up).
// 256 threads, 8 warps (4M x 2N), 2 CTAs/SM.  2-stage cp.async pipeline.
// ---------------------------------------------------------------------------
#define NCH1 (H_DIM / KC)   // 16

__global__ __launch_bounds__(256, 2)
void gemm1(void) {
    const int e   = blockIdx.z;
    const int cnt = g_count[e];
    const int m0  = blockIdx.x * 128;
    if (m0 >= cnt) return;
    const int off  = g_offset[e];
    const int n0g  = blockIdx.y * 64;
    const int cntm = cnt - m0;

    extern __shared__ __half smem[];
    __shared__ int rowtok[128];
    const uint32_t sb = smem_u32(smem);

    const int tid = threadIdx.x, lane = tid & 31, wid = tid >> 5;
    const int wm = wid & 3, wn = wid >> 2;

    if (tid < 128)
        rowtok[tid] = (tid < cntm) ? g_perm[off + m0 + tid] / K_TOP : -1;
    __syncthreads();

    const __half* wb = g_wgu + (size_t)e * (2 * I_DIM) * H_DIM;

    auto issue = [&](int k0, int soE) {
        #pragma unroll
        for (int i = 0; i < 8; i++) {
            int idx = tid + i * 256;
            int mat = idx >> 10;             // 0=A 1=B
            int row = (idx >> 3) & 127;
            int seg = idx & 7;
            uint32_t dst = sb + (uint32_t)(soE + mat * TILE_E + row * STRIDE + seg * 8) * 2;
            if (mat == 0) {
                int tok = rowtok[row];
                const __half* src = g_x + (size_t)(tok < 0 ? 0 : tok) * H_DIM + k0 + seg * 8;
                CP_ASYNC16(dst, src, (tok < 0) ? 0u : 16u);
            } else {
                int wr = (row < 64) ? (n0g + row) : (I_DIM + n0g + row - 64);
                const __half* src = wb + (size_t)wr * H_DIM + k0 + seg * 8;
                CP_ASYNC16(dst, src, 16u);
            }
        }
        CP_COMMIT;
    };

    float accG[2][4][4], accU[2][4][4];
    #pragma unroll
    for (int a = 0; a < 2; a++)
        #pragma unroll
        for (int b = 0; b < 4; b++)
            #pragma unroll
            for (int c = 0; c < 4; c++) { accG[a][b][c] = 0.f; accU[a][b][c] = 0.f; }

    issue(0, 0);

    for (int c = 0; c < NCH1; c++) {
        const int s = c & 1;
        if (c + 1 < NCH1) { issue((c + 1) * KC, (s ^ 1) * STAGE_E); CP_WAIT1; }
        else CP_WAIT0;
        __syncthreads();

        const int so = s * STAGE_E;
        #pragma unroll
        for (int kk = 0; kk < KC; kk += 16) {
            uint32_t ah[2][4], bg[2][4], bu[2][4];
            #pragma unroll
            for (int mt = 0; mt < 2; mt++)
                load_afrag(sb, so, wm * 32 + mt * 16, kk, lane, ah[mt]);
            #pragma unroll
            for (int p = 0; p < 2; p++) {
                load_bfrag(sb, so + TILE_E, wn * 32 + p * 16,      kk, lane, bg[p]);
                load_bfrag(sb, so + TILE_E, wn * 32 + p * 16 + 64, kk, lane, bu[p]);
            }
            #pragma unroll
            for (int p = 0; p < 2; p++) {
                #pragma unroll
                for (int mt = 0; mt < 2; mt++) {
                    #pragma unroll
                    for (int q = 0; q < 2; q++) {
                        MMA_F16(accG[mt][2 * p + q], ah[mt], bg[p][2 * q], bg[p][2 * q + 1]);
                        MMA_F16(accU[mt][2 * p + q], ah[mt], bu[p][2 * q], bu[p][2 * q + 1]);
                    }
                }
            }
        }
        __syncthreads();
    }

    // epilogue: silu(gate)*up -> fp16 act
    const int gid = lane >> 2, tig = lane & 3;
    #pragma unroll
    for (int mt = 0; mt < 2; mt++) {
        #pragma unroll
        for (int nt = 0; nt < 4; nt++) {
            int colg = n0g + wn * 32 + nt * 8 + 2 * tig;
            #pragma unroll
            for (int h = 0; h < 2; h++) {
                int rowl = wm * 32 + mt * 16 + gid + h * 8;
                if (rowl < cntm) {
                    float g0 = accG[mt][nt][2 * h],     u0 = accU[mt][nt][2 * h];
                    float g1 = accG[mt][nt][2 * h + 1], u1 = accU[mt][nt][2 * h + 1];
                    float v0 = (g0 / (1.f + __expf(-g0))) * u0;
                    float v1 = (g1 / (1.f + __expf(-g1))) * u1;
                    size_t o = (size_t)(off + m0 + rowl) * I_DIM + colg;
                    *(uint32_t*)(g_act + o) = pack_h2(__float2half_rn(v0), __float2half_rn(v1));
                }
            }
        }
    }
}

// ---------------------------------------------------------------------------
// GEMM2 + fused combine: out[t,:] += w * (act * Wd^T).  Block 128 x 128 H.
// 2-stage cp.async pipeline.
// ---------------------------------------------------------------------------
#define NCH2 (I_DIM / KC)   // 12

__global__ __launch_bounds__(256, 2)
void gemm2(const float* __restrict__ wts, float* __restrict__ out) {
    const int e   = blockIdx.z;
    const int cnt = g_count[e];
    const int m0  = blockIdx.x * 128;
    if (m0 >= cnt) return;
    const int off  = g_offset[e];
    const int n0   = blockIdx.y * 128;
    const int cntm = cnt - m0;

    extern __shared__ __half smem[];
    const uint32_t sb = smem_u32(smem);

    const int tid = threadIdx.x, lane = tid & 31, wid = tid >> 5;
    const int wm = wid & 3, wn = wid >> 2;

    const __half* wb = g_wd + (size_t)e * H_DIM * I_DIM;

    auto issue = [&](int k0, int soE) {
        #pragma unroll
        for (int i = 0; i < 8; i++) {
            int idx = tid + i * 256;
            int mat = idx >> 10;
            int row = (idx >> 3) & 127;
            int seg = idx & 7;
            uint32_t dst = sb + (uint32_t)(soE + mat * TILE_E + row * STRIDE + seg * 8) * 2;
            if (mat == 0) {
                int r = (row < cntm) ? row : 0;
                const __half* src = g_act + (size_t)(off + m0 + r) * I_DIM + k0 + seg * 8;
                CP_ASYNC16(dst, src, (row < cntm) ? 16u : 0u);
            } else {
                const __half* src = wb + (size_t)(n0 + row) * I_DIM + k0 + seg * 8;
                CP_ASYNC16(dst, src, 16u);
            }
        }
        CP_COMMIT;
    };

    float acc[2][8][4];
    #pragma unroll
    for (int a = 0; a < 2; a++)
        #pragma unroll
        for (int b = 0; b < 8; b++)
            #pragma unroll
            for (int c = 0; c < 4; c++) acc[a][b][c] = 0.f;

    issue(0, 0);

    for (int c = 0; c < NCH2; c++) {
        const int s = c & 1;
        if (c + 1 < NCH2) { issue((c + 1) * KC, (s ^ 1) * STAGE_E); CP_WAIT1; }
        else CP_WAIT0;
        __syncthreads();

        const int so = s * STAGE_E;
        #pragma unroll
        for (int kk = 0; kk < KC; kk += 16) {
            uint32_t ah[2][4], bh[4][4];
            #pragma unroll
            for (int mt = 0; mt < 2; mt++)
                load_afrag(sb, so, wm * 32 + mt * 16, kk, lane, ah[mt]);
            #pragma unroll
            for (int p = 0; p < 4; p++)
                load_bfrag(sb, so + TILE_E, wn * 64 + p * 16, kk, lane, bh[p]);
            #pragma unroll
            for (int p = 0; p < 4; p++) {
                #pragma unroll
                for (int mt = 0; mt < 2; mt++) {
                    #pragma unroll
                    for (int q = 0; q < 2; q++)
                        MMA_F16(acc[mt][2 * p + q], ah[mt], bh[p][2 * q], bh[p][2 * q + 1]);
                }
            }
        }
        __syncthreads();
    }

    // fused combine epilogue: out[t, col] += w * acc  via vector atomics
    const int gid = lane >> 2, tig = lane & 3;
    #pragma unroll
    for (int mt = 0; mt < 2; mt++) {
        #pragma unroll
        for (int h = 0; h < 2; h++) {
            int rowl = wm * 32 + mt * 16 + gid + h * 8;
            if (rowl < cntm) {
                int a = g_perm[off + m0 + rowl];
                int t = a / K_TOP;
                float w = wts[a];
                float* obase = out + (size_t)t * H_DIM;
                #pragma unroll
                for (int nt = 0; nt < 8; nt++) {
                    int col = n0 + wn * 64 + nt * 8 + 2 * tig;
                    float2 r = make_float2(w * acc[mt][nt][2 * h],
                                           w * acc[mt][nt][2 * h + 1]);
                    atomicAdd((float2*)(obase + col), r);
                }
            }
        }
    }
}

// ---------------------------------------------------------------------------
// Launch
// ---------------------------------------------------------------------------
extern "C" void kernel_launch(void* const* d_in, const int* in_sizes, int n_in,
                              void* d_out, int out_size) {
    const float* X    = (const float*)d_in[0];
    const float* Wgu  = (const float*)d_in[1];
    const float* Wd   = (const float*)d_in[2];
    const int*   topk = (const int*)  d_in[3];
    const float* wts  = (const float*)d_in[4];
    float*       out  = (float*)d_out;

    cudaFuncSetAttribute(gemm1, cudaFuncAttributeMaxDynamicSharedMemorySize, SMEM_BYTES);
    cudaFuncSetAttribute(gemm2, cudaFuncAttributeMaxDynamicSharedMemorySize, SMEM_BYTES);

    route_all<<<1, 1024>>>(topk);
    conv_all<<<1024, 256>>>(X, Wgu, Wd, out);

    dim3 g1(A_TOT / 128, I_DIM / 64, E_NUM);    // (32, 12, 8)
    gemm1<<<g1, 256, SMEM_BYTES>>>();

    dim3 g2(A_TOT / 128, H_DIM / 128, E_NUM);   // (32, 8, 8)
    gemm2<<<g2, 256, SMEM_BYTES>>>(wts, out);
}

// round 13
// speedup vs baseline: 1.0946x; 1.0398x over previous
#include <cuda_runtime.h>
#include <cuda_fp16.h>
#include <stdint.h>

// Problem constants
#define T_TOK 2048
#define H_DIM 1024
#define I_DIM 768
#define E_NUM 8
#define K_TOP 2
#define A_TOT (T_TOK * K_TOP)   // 4096
#define MAXBLK 40               // A_TOT/128 + E_NUM

// ---------------------------------------------------------------------------
// Device-global scratch
// ---------------------------------------------------------------------------
__device__ int   g_count[E_NUM];
__device__ int   g_offset[E_NUM];
__device__ int   g_perm[A_TOT];
__device__ int   g_nblk;
__device__ int   g_be[MAXBLK];
__device__ int   g_bm[MAXBLK];
__device__ __half g_x  [(size_t)T_TOK * H_DIM];
__device__ __half g_wgu[(size_t)E_NUM * 2 * I_DIM * H_DIM];
__device__ __half g_wd [(size_t)E_NUM * H_DIM * I_DIM];
__device__ __half g_act[(size_t)A_TOT * I_DIM];

// ---------------------------------------------------------------------------
// PTX helpers
// ---------------------------------------------------------------------------
__device__ __forceinline__ uint32_t smem_u32(const void* p) {
    uint32_t a;
    asm("{ .reg .u64 t; cvta.to.shared.u64 t, %1; cvt.u32.u64 %0, t; }" : "=r"(a) : "l"(p));
    return a;
}

#define LDSM_X4(R0, R1, R2, R3, ADDR) \
    asm volatile("ldmatrix.sync.aligned.m8n8.x4.shared.b16 {%0,%1,%2,%3}, [%4];" \
        : "=r"(R0), "=r"(R1), "=r"(R2), "=r"(R3) : "r"(ADDR))

#define MMA_F16(D, A, B0, B1) \
    asm volatile("mma.sync.aligned.m16n8k16.row.col.f32.f16.f16.f32 " \
        "{%0,%1,%2,%3}, {%4,%5,%6,%7}, {%8,%9}, {%0,%1,%2,%3};" \
        : "+f"((D)[0]), "+f"((D)[1]), "+f"((D)[2]), "+f"((D)[3]) \
        : "r"((A)[0]), "r"((A)[1]), "r"((A)[2]), "r"((A)[3]), "r"(B0), "r"(B1))

#define CP_ASYNC16(DST, SRC, SZ) \
    asm volatile("cp.async.cg.shared.global [%0], [%1], 16, %2;" \
        :: "r"(DST), "l"(SRC), "r"(SZ))
#define CP_COMMIT  asm volatile("cp.async.commit_group;" ::: "memory")
#define CP_WAIT1   asm volatile("cp.async.wait_group 1;" ::: "memory")
#define CP_WAIT0   asm volatile("cp.async.wait_group 0;" ::: "memory")

__device__ __forceinline__ uint32_t pack_h2(__half a, __half b) {
    return (uint32_t)__half_as_ushort(a) | ((uint32_t)__half_as_ushort(b) << 16);
}

// ---------------------------------------------------------------------------
// Fused conversion + routing + output-zero kernel.
// Blocks 0..1023 (262144 threads): exact-trip-count fp32->fp16 streams + zero.
// Block 1024: routing (counts, offsets, permutation, block mapping table).
// ---------------------------------------------------------------------------
#define CVT_THREADS 262144
#define NG4  (E_NUM * 2 * I_DIM * H_DIM / 4)   // 3145728 -> 12 iters
#define ND4  (E_NUM * H_DIM * I_DIM / 4)       // 1572864 -> 6 iters
#define NX4  (T_TOK * H_DIM / 4)               // 524288  -> 2 iters

__global__ void prep_all(const float* __restrict__ X,
                         const float* __restrict__ Wgu,
                         const float* __restrict__ Wd,
                         const int* __restrict__ topk,
                         float* __restrict__ out) {
    __shared__ int cnt[E_NUM], cur[E_NUM];
    const int tid = threadIdx.x;

    if (blockIdx.x == 1024) {
        // ---- routing block ----
        if (tid < E_NUM) cnt[tid] = 0;
        __syncthreads();
        for (int a = tid; a < A_TOT; a += 256) atomicAdd(&cnt[topk[a]], 1);
        __syncthreads();
        if (tid == 0) {
            int s = 0, idx = 0;
            for (int e = 0; e < E_NUM; e++) {
                g_count[e] = cnt[e];
                g_offset[e] = s;
                cur[e] = s;
                s += cnt[e];
                for (int mb = 0; mb * 128 < cnt[e]; mb++) {
                    g_be[idx] = e;
                    g_bm[idx] = mb * 128;
                    idx++;
                }
            }
            g_nblk = idx;
        }
        __syncthreads();
        for (int a = tid; a < A_TOT; a += 256) {
            int e = topk[a];
            int s = atomicAdd(&cur[e], 1);
            g_perm[s] = a;
        }
        return;
    }

    // ---- conversion blocks ----
    const int t = blockIdx.x * blockDim.x + tid;
    #pragma unroll
    for (int j = 0; j < 12; j++) {
        int i = t + j * CVT_THREADS;
        float4 v = ((const float4*)Wgu)[i];
        uint2 u;
        u.x = pack_h2(__float2half_rn(v.x), __float2half_rn(v.y));
        u.y = pack_h2(__float2half_rn(v.z), __float2half_rn(v.w));
        ((uint2*)g_wgu)[i] = u;
    }
    #pragma unroll
    for (int j = 0; j < 6; j++) {
        int i = t + j * CVT_THREADS;
        float4 v = ((const float4*)Wd)[i];
        uint2 u;
        u.x = pack_h2(__float2half_rn(v.x), __float2half_rn(v.y));
        u.y = pack_h2(__float2half_rn(v.z), __float2half_rn(v.w));
        ((uint2*)g_wd)[i] = u;
    }
    #pragma unroll
    for (int j = 0; j < 2; j++) {
        int i = t + j * CVT_THREADS;
        float4 v = ((const float4*)X)[i];
        uint2 u;
        u.x = pack_h2(__float2half_rn(v.x), __float2half_rn(v.y));
        u.y = pack_h2(__float2half_rn(v.z), __float2half_rn(v.w));
        ((uint2*)g_x)[i] = u;
    }
    #pragma unroll
    for (int j = 0; j < 2; j++) {
        int i = t + j * CVT_THREADS;
        ((float4*)out)[i] = make_float4(0.f, 0.f, 0.f, 0.f);
    }
}

// ---------------------------------------------------------------------------
// SMEM: KC=64 fp16 cols, stride 72 (conflict-free ldmatrix), 2 stages.
// Per stage: A(128x72) | B(128x72) = 36 KB.  2 stages = 72 KB/CTA, 2 CTAs/SM.
// ---------------------------------------------------------------------------
#define KC       64
#define STRIDE   72
#define TILE_E   (128 * STRIDE)       // 9216 elems
#define STAGE_E  (2 * TILE_E)         // 18432
#define SMEM_BYTES (2 * STAGE_E * 2)  // 73728 B

__device__ __forceinline__ void load_afrag(uint32_t sb, int eoff, int row0, int kk,
                                           int lane, uint32_t a[4]) {
    int row = row0 + (lane & 15);
    int col = kk + ((lane >> 4) << 3);
    uint32_t addr = sb + (uint32_t)(eoff + row * STRIDE + col) * 2;
    LDSM_X4(a[0], a[1], a[2], a[3], addr);
}
__device__ __forceinline__ void load_bfrag(uint32_t sb, int eoff, int nbase, int kk,
                                           int lane, uint32_t b[4]) {
    int row = nbase + (((lane >> 4) & 1) << 3) + (lane & 7);
    int col = kk + (((lane >> 3) & 1) << 3);
    uint32_t addr = sb + (uint32_t)(eoff + row * STRIDE + col) * 2;
    LDSM_X4(b[0], b[1], b[2], b[3], addr);
}

// ---------------------------------------------------------------------------
// GEMM1: act = silu(X*Wg^T) * (X*Wu^T).  Compact grid (MAXBLK, 12).
// Block 128 slots x (64 gate + 64 up).  256 threads, 2 CTAs/SM, 2-stage.
// ---------------------------------------------------------------------------
#define NCH1 (H_DIM / KC)   // 16

__global__ __launch_bounds__(256, 2)
void gemm1(void) {
    if (blockIdx.x >= g_nblk) return;
    const int e    = g_be[blockIdx.x];
    const int m0   = g_bm[blockIdx.x];
    const int cnt  = g_count[e];
    const int off  = g_offset[e];
    const int n0g  = blockIdx.y * 64;
    const int cntm = cnt - m0;

    extern __shared__ __half smem[];
    __shared__ int rowtok[128];
    const uint32_t sb = smem_u32(smem);

    const int tid = threadIdx.x, lane = tid & 31, wid = tid >> 5;
    const int wm = wid & 3, wn = wid >> 2;

    if (tid < 128)
        rowtok[tid] = (tid < cntm) ? g_perm[off + m0 + tid] / K_TOP : -1;
    __syncthreads();

    const __half* wb = g_wgu + (size_t)e * (2 * I_DIM) * H_DIM;

    auto issue = [&](int k0, int soE) {
        #pragma unroll
        for (int i = 0; i < 8; i++) {
            int idx = tid + i * 256;
            int mat = idx >> 10;             // 0=A 1=B
            int row = (idx >> 3) & 127;
            int seg = idx & 7;
            uint32_t dst = sb + (uint32_t)(soE + mat * TILE_E + row * STRIDE + seg * 8) * 2;
            if (mat == 0) {
                int tok = rowtok[row];
                const __half* src = g_x + (size_t)(tok < 0 ? 0 : tok) * H_DIM + k0 + seg * 8;
                CP_ASYNC16(dst, src, (tok < 0) ? 0u : 16u);
            } else {
                int wr = (row < 64) ? (n0g + row) : (I_DIM + n0g + row - 64);
                const __half* src = wb + (size_t)wr * H_DIM + k0 + seg * 8;
                CP_ASYNC16(dst, src, 16u);
            }
        }
        CP_COMMIT;
    };

    float accG[2][4][4], accU[2][4][4];
    #pragma unroll
    for (int a = 0; a < 2; a++)
        #pragma unroll
        for (int b = 0; b < 4; b++)
            #pragma unroll
            for (int c = 0; c < 4; c++) { accG[a][b][c] = 0.f; accU[a][b][c] = 0.f; }

    issue(0, 0);

    for (int c = 0; c < NCH1; c++) {
        const int s = c & 1;
        if (c + 1 < NCH1) { issue((c + 1) * KC, (s ^ 1) * STAGE_E); CP_WAIT1; }
        else CP_WAIT0;
        __syncthreads();

        const int so = s * STAGE_E;
        #pragma unroll
        for (int kk = 0; kk < KC; kk += 16) {
            uint32_t ah[2][4], bg[2][4], bu[2][4];
            #pragma unroll
            for (int mt = 0; mt < 2; mt++)
                load_afrag(sb, so, wm * 32 + mt * 16, kk, lane, ah[mt]);
            #pragma unroll
            for (int p = 0; p < 2; p++) {
                load_bfrag(sb, so + TILE_E, wn * 32 + p * 16,      kk, lane, bg[p]);
                load_bfrag(sb, so + TILE_E, wn * 32 + p * 16 + 64, kk, lane, bu[p]);
            }
            #pragma unroll
            for (int p = 0; p < 2; p++) {
                #pragma unroll
                for (int mt = 0; mt < 2; mt++) {
                    #pragma unroll
                    for (int q = 0; q < 2; q++) {
                        MMA_F16(accG[mt][2 * p + q], ah[mt], bg[p][2 * q], bg[p][2 * q + 1]);
                        MMA_F16(accU[mt][2 * p + q], ah[mt], bu[p][2 * q], bu[p][2 * q + 1]);
                    }
                }
            }
        }
        __syncthreads();
    }

    // epilogue: silu(gate)*up -> fp16 act
    const int gid = lane >> 2, tig = lane & 3;
    #pragma unroll
    for (int mt = 0; mt < 2; mt++) {
        #pragma unroll
        for (int nt = 0; nt < 4; nt++) {
            int colg = n0g + wn * 32 + nt * 8 + 2 * tig;
            #pragma unroll
            for (int h = 0; h < 2; h++) {
                int rowl = wm * 32 + mt * 16 + gid + h * 8;
                if (rowl < cntm) {
                    float g0 = accG[mt][nt][2 * h],     u0 = accU[mt][nt][2 * h];
                    float g1 = accG[mt][nt][2 * h + 1], u1 = accU[mt][nt][2 * h + 1];
                    float v0 = (g0 / (1.f + __expf(-g0))) * u0;
                    float v1 = (g1 / (1.f + __expf(-g1))) * u1;
                    size_t o = (size_t)(off + m0 + rowl) * I_DIM + colg;
                    *(uint32_t*)(g_act + o) = pack_h2(__float2half_rn(v0), __float2half_rn(v1));
                }
            }
        }
    }
}

// ---------------------------------------------------------------------------
// GEMM2 + fused combine: out[t,:] += w * (act * Wd^T).  Compact grid (MAXBLK, 8).
// ---------------------------------------------------------------------------
#define NCH2 (I_DIM / KC)   // 12

__global__ __launch_bounds__(256, 2)
void gemm2(const float* __restrict__ wts, float* __restrict__ out) {
    if (blockIdx.x >= g_nblk) return;
    const int e    = g_be[blockIdx.x];
    const int m0   = g_bm[blockIdx.x];
    const int cnt  = g_count[e];
    const int off  = g_offset[e];
    const int n0   = blockIdx.y * 128;
    const int cntm = cnt - m0;

    extern __shared__ __half smem[];
    const uint32_t sb = smem_u32(smem);

    const int tid = threadIdx.x, lane = tid & 31, wid = tid >> 5;
    const int wm = wid & 3, wn = wid >> 2;

    const __half* wb = g_wd + (size_t)e * H_DIM * I_DIM;

    auto issue = [&](int k0, int soE) {
        #pragma unroll
        for (int i = 0; i < 8; i++) {
            int idx = tid + i * 256;
            int mat = idx >> 10;
            int row = (idx >> 3) & 127;
            int seg = idx & 7;
            uint32_t dst = sb + (uint32_t)(soE + mat * TILE_E + row * STRIDE + seg * 8) * 2;
            if (mat == 0) {
                int r = (row < cntm) ? row : 0;
                const __half* src = g_act + (size_t)(off + m0 + r) * I_DIM + k0 + seg * 8;
                CP_ASYNC16(dst, src, (row < cntm) ? 16u : 0u);
            } else {
                const __half* src = wb + (size_t)(n0 + row) * I_DIM + k0 + seg * 8;
                CP_ASYNC16(dst, src, 16u);
            }
        }
        CP_COMMIT;
    };

    float acc[2][8][4];
    #pragma unroll
    for (int a = 0; a < 2; a++)
        #pragma unroll
        for (int b = 0; b < 8; b++)
            #pragma unroll
            for (int c = 0; c < 4; c++) acc[a][b][c] = 0.f;

    issue(0, 0);

    for (int c = 0; c < NCH2; c++) {
        const int s = c & 1;
        if (c + 1 < NCH2) { issue((c + 1) * KC, (s ^ 1) * STAGE_E); CP_WAIT1; }
        else CP_WAIT0;
        __syncthreads();

        const int so = s * STAGE_E;
        #pragma unroll
        for (int kk = 0; kk < KC; kk += 16) {
            uint32_t ah[2][4], bh[4][4];
            #pragma unroll
            for (int mt = 0; mt < 2; mt++)
                load_afrag(sb, so, wm * 32 + mt * 16, kk, lane, ah[mt]);
            #pragma unroll
            for (int p = 0; p < 4; p++)
                load_bfrag(sb, so + TILE_E, wn * 64 + p * 16, kk, lane, bh[p]);
            #pragma unroll
            for (int p = 0; p < 4; p++) {
                #pragma unroll
                for (int mt = 0; mt < 2; mt++) {
                    #pragma unroll
                    for (int q = 0; q < 2; q++)
                        MMA_F16(acc[mt][2 * p + q], ah[mt], bh[p][2 * q], bh[p][2 * q + 1]);
                }
            }
        }
        __syncthreads();
    }

    // fused combine epilogue: out[t, col] += w * acc via vector atomics
    const int gid = lane >> 2, tig = lane & 3;
    #pragma unroll
    for (int mt = 0; mt < 2; mt++) {
        #pragma unroll
        for (int h = 0; h < 2; h++) {
            int rowl = wm * 32 + mt * 16 + gid + h * 8;
            if (rowl < cntm) {
                int a = g_perm[off + m0 + rowl];
                int t = a / K_TOP;
                float w = wts[a];
                float* obase = out + (size_t)t * H_DIM;
                #pragma unroll
                for (int nt = 0; nt < 8; nt++) {
                    int col = n0 + wn * 64 + nt * 8 + 2 * tig;
                    float2 r = make_float2(w * acc[mt][nt][2 * h],
                                           w * acc[mt][nt][2 * h + 1]);
                    atomicAdd((float2*)(obase + col), r);
                }
            }
        }
    }
}

// ---------------------------------------------------------------------------
// Launch
// ---------------------------------------------------------------------------
extern "C" void kernel_launch(void* const* d_in, const int* in_sizes, int n_in,
                              void* d_out, int out_size) {
    const float* X    = (const float*)d_in[0];
    const float* Wgu  = (const float*)d_in[1];
    const float* Wd   = (const float*)d_in[2];
    const int*   topk = (const int*)  d_in[3];
    const float* wts  = (const float*)d_in[4];
    float*       out  = (float*)d_out;

    cudaFuncSetAttribute(gemm1, cudaFuncAttributeMaxDynamicSharedMemorySize, SMEM_BYTES);
    cudaFuncSetAttribute(gemm2, cudaFuncAttributeMaxDynamicSharedMemorySize, SMEM_BYTES);

    prep_all<<<1025, 256>>>(X, Wgu, Wd, topk, out);

    dim3 g1(MAXBLK, I_DIM / 64);    // (40, 12)
    gemm1<<<g1, 256, SMEM_BYTES>>>();

    dim3 g2(MAXBLK, H_DIM / 128);   // (40, 8)
    gemm2<<<g2, 256, SMEM_BYTES>>>(wts, out);
}

// round 15
// speedup vs baseline: 1.1130x; 1.0168x over previous
#include <cuda_runtime.h>
#include <cuda_fp16.h>
#include <stdint.h>

// Problem constants
#define T_TOK 2048
#define H_DIM 1024
#define I_DIM 768
#define E_NUM 8
#define K_TOP 2
#define A_TOT (T_TOK * K_TOP)   // 4096
#define MAXBLK 40               // A_TOT/128 + E_NUM
#define NT1 12                  // gemm1 column tiles per row block (I/64)
#define NT2 8                   // gemm2 column tiles per row block (H/128)

// ---------------------------------------------------------------------------
// Device-global scratch
// ---------------------------------------------------------------------------
__device__ int   g_count[E_NUM];
__device__ int   g_offset[E_NUM];
__device__ int   g_perm[A_TOT];
__device__ int   g_nblk;
__device__ int   g_be[MAXBLK];
__device__ int   g_bm[MAXBLK];
__device__ int   g_ticket;
__device__ int   g_flag[MAXBLK];
__device__ __half g_x  [(size_t)T_TOK * H_DIM];
__device__ __half g_wgu[(size_t)E_NUM * 2 * I_DIM * H_DIM];
__device__ __half g_wd [(size_t)E_NUM * H_DIM * I_DIM];
__device__ __half g_act[(size_t)A_TOT * I_DIM];

// ---------------------------------------------------------------------------
// PTX helpers
// ---------------------------------------------------------------------------
__device__ __forceinline__ uint32_t smem_u32(const void* p) {
    uint32_t a;
    asm("{ .reg .u64 t; cvta.to.shared.u64 t, %1; cvt.u32.u64 %0, t; }" : "=r"(a) : "l"(p));
    return a;
}

#define LDSM_X4(R0, R1, R2, R3, ADDR) \
    asm volatile("ldmatrix.sync.aligned.m8n8.x4.shared.b16 {%0,%1,%2,%3}, [%4];" \
        : "=r"(R0), "=r"(R1), "=r"(R2), "=r"(R3) : "r"(ADDR))

#define MMA_F16(D, A, B0, B1) \
    asm volatile("mma.sync.aligned.m16n8k16.row.col.f32.f16.f16.f32 " \
        "{%0,%1,%2,%3}, {%4,%5,%6,%7}, {%8,%9}, {%0,%1,%2,%3};" \
        : "+f"((D)[0]), "+f"((D)[1]), "+f"((D)[2]), "+f"((D)[3]) \
        : "r"((A)[0]), "r"((A)[1]), "r"((A)[2]), "r"((A)[3]), "r"(B0), "r"(B1))

#define CP_ASYNC16(DST, SRC, SZ) \
    asm volatile("cp.async.cg.shared.global [%0], [%1], 16, %2;" \
        :: "r"(DST), "l"(SRC), "r"(SZ))
#define CP_COMMIT  asm volatile("cp.async.commit_group;" ::: "memory")
#define CP_WAIT1   asm volatile("cp.async.wait_group 1;" ::: "memory")
#define CP_WAIT0   asm volatile("cp.async.wait_group 0;" ::: "memory")

__device__ __forceinline__ uint32_t pack_h2(__half a, __half b) {
    return (uint32_t)__half_as_ushort(a) | ((uint32_t)__half_as_ushort(b) << 16);
}

// ---------------------------------------------------------------------------
// Fused conversion + routing + output-zero kernel.
// Blocks 0..1023: exact-trip-count fp32->fp16 streams + zero.
// Block 1024: routing + work-queue reset.
// ---------------------------------------------------------------------------
#define CVT_THREADS 262144

__global__ void prep_all(const float* __restrict__ X,
                         const float* __restrict__ Wgu,
                         const float* __restrict__ Wd,
                         const int* __restrict__ topk,
                         float* __restrict__ out) {
    __shared__ int cnt[E_NUM], cur[E_NUM];
    const int tid = threadIdx.x;

    if (blockIdx.x == 1024) {
        if (tid < E_NUM) cnt[tid] = 0;
        if (tid < MAXBLK) g_flag[tid] = 0;
        if (tid == 0) g_ticket = 0;
        __syncthreads();
        for (int a = tid; a < A_TOT; a += 256) atomicAdd(&cnt[topk[a]], 1);
        __syncthreads();
        if (tid == 0) {
            int s = 0, idx = 0;
            for (int e = 0; e < E_NUM; e++) {
                g_count[e] = cnt[e];
                g_offset[e] = s;
                cur[e] = s;
                s += cnt[e];
                for (int mb = 0; mb * 128 < cnt[e]; mb++) {
                    g_be[idx] = e;
                    g_bm[idx] = mb * 128;
                    idx++;
                }
            }
            g_nblk = idx;
        }
        __syncthreads();
        for (int a = tid; a < A_TOT; a += 256) {
            int e = topk[a];
            int s = atomicAdd(&cur[e], 1);
            g_perm[s] = a;
        }
        return;
    }

    const int t = blockIdx.x * blockDim.x + tid;
    #pragma unroll
    for (int j = 0; j < 12; j++) {
        int i = t + j * CVT_THREADS;
        float4 v = ((const float4*)Wgu)[i];
        uint2 u;
        u.x = pack_h2(__float2half_rn(v.x), __float2half_rn(v.y));
        u.y = pack_h2(__float2half_rn(v.z), __float2half_rn(v.w));
        ((uint2*)g_wgu)[i] = u;
    }
    #pragma unroll
    for (int j = 0; j < 6; j++) {
        int i = t + j * CVT_THREADS;
        float4 v = ((const float4*)Wd)[i];
        uint2 u;
        u.x = pack_h2(__float2half_rn(v.x), __float2half_rn(v.y));
        u.y = pack_h2(__float2half_rn(v.z), __float2half_rn(v.w));
        ((uint2*)g_wd)[i] = u;
    }
    #pragma unroll
    for (int j = 0; j < 2; j++) {
        int i = t + j * CVT_THREADS;
        float4 v = ((const float4*)X)[i];
        uint2 u;
        u.x = pack_h2(__float2half_rn(v.x), __float2half_rn(v.y));
        u.y = pack_h2(__float2half_rn(v.z), __float2half_rn(v.w));
        ((uint2*)g_x)[i] = u;
    }
    #pragma unroll
    for (int j = 0; j < 2; j++) {
        int i = t + j * CVT_THREADS;
        ((float4*)out)[i] = make_float4(0.f, 0.f, 0.f, 0.f);
    }
}

// ---------------------------------------------------------------------------
// SMEM: KC=64 fp16 cols, stride 72 (conflict-free ldmatrix), 2 stages.
// Per stage: A(128x72) | B(128x72) = 36 KB.  2 stages = 72 KB/CTA, 2 CTAs/SM.
// ---------------------------------------------------------------------------
#define KC       64
#define STRIDE   72
#define TILE_E   (128 * STRIDE)       // 9216 elems
#define STAGE_E  (2 * TILE_E)         // 18432
#define SMEM_BYTES (2 * STAGE_E * 2)  // 73728 B

__device__ __forceinline__ void load_afrag(uint32_t sb, int eoff, int row0, int kk,
                                           int lane, uint32_t a[4]) {
    int row = row0 + (lane & 15);
    int col = kk + ((lane >> 4) << 3);
    uint32_t addr = sb + (uint32_t)(eoff + row * STRIDE + col) * 2;
    LDSM_X4(a[0], a[1], a[2], a[3], addr);
}
__device__ __forceinline__ void load_bfrag(uint32_t sb, int eoff, int nbase, int kk,
                                           int lane, uint32_t b[4]) {
    int row = nbase + (((lane >> 4) & 1) << 3) + (lane & 7);
    int col = kk + (((lane >> 3) & 1) << 3);
    uint32_t addr = sb + (uint32_t)(eoff + row * STRIDE + col) * 2;
    LDSM_X4(b[0], b[1], b[2], b[3], addr);
}

#define NCH1 (H_DIM / KC)   // 16
#define NCH2 (I_DIM / KC)   // 12

// ---------------------------------------------------------------------------
// GEMM1 body: act = silu(X*Wg^T)*(X*Wu^T) for (bx, n0g).  On completion,
// bumps g_flag[bx].
// ---------------------------------------------------------------------------
__device__ void gemm1_body(int bx, int n0g, char* smem_raw) {
    const int e    = g_be[bx];
    const int m0   = g_bm[bx];
    const int cnt  = g_count[e];
    const int off  = g_offset[e];
    const int cntm = cnt - m0;

    __half* smem = (__half*)smem_raw;
    __shared__ int rowtok[128];
    const uint32_t sb = smem_u32(smem);

    const int tid = threadIdx.x, lane = tid & 31, wid = tid >> 5;
    const int wm = wid & 3, wn = wid >> 2;

    if (tid < 128)
        rowtok[tid] = (tid < cntm) ? g_perm[off + m0 + tid] / K_TOP : -1;
    __syncthreads();

    const __half* wb = g_wgu + (size_t)e * (2 * I_DIM) * H_DIM;

    auto issue = [&](int k0, int soE) {
        #pragma unroll
        for (int i = 0; i < 8; i++) {
            int idx = tid + i * 256;
            int mat = idx >> 10;             // 0=A 1=B
            int row = (idx >> 3) & 127;
            int seg = idx & 7;
            uint32_t dst = sb + (uint32_t)(soE + mat * TILE_E + row * STRIDE + seg * 8) * 2;
            if (mat == 0) {
                int tok = rowtok[row];
                const __half* src = g_x + (size_t)(tok < 0 ? 0 : tok) * H_DIM + k0 + seg * 8;
                CP_ASYNC16(dst, src, (tok < 0) ? 0u : 16u);
            } else {
                int wr = (row < 64) ? (n0g + row) : (I_DIM + n0g + row - 64);
                const __half* src = wb + (size_t)wr * H_DIM + k0 + seg * 8;
                CP_ASYNC16(dst, src, 16u);
            }
        }
        CP_COMMIT;
    };

    float accG[2][4][4], accU[2][4][4];
    #pragma unroll
    for (int a = 0; a < 2; a++)
        #pragma unroll
        for (int b = 0; b < 4; b++)
            #pragma unroll
            for (int c = 0; c < 4; c++) { accG[a][b][c] = 0.f; accU[a][b][c] = 0.f; }

    issue(0, 0);

    for (int c = 0; c < NCH1; c++) {
        const int s = c & 1;
        if (c + 1 < NCH1) { issue((c + 1) * KC, (s ^ 1) * STAGE_E); CP_WAIT1; }
        else CP_WAIT0;
        __syncthreads();

        const int so = s * STAGE_E;
        #pragma unroll
        for (int kk = 0; kk < KC; kk += 16) {
            uint32_t ah[2][4], bg[2][4], bu[2][4];
            #pragma unroll
            for (int mt = 0; mt < 2; mt++)
                load_afrag(sb, so, wm * 32 + mt * 16, kk, lane, ah[mt]);
            #pragma unroll
            for (int p = 0; p < 2; p++) {
                load_bfrag(sb, so + TILE_E, wn * 32 + p * 16,      kk, lane, bg[p]);
                load_bfrag(sb, so + TILE_E, wn * 32 + p * 16 + 64, kk, lane, bu[p]);
            }
            #pragma unroll
            for (int p = 0; p < 2; p++) {
                #pragma unroll
                for (int mt = 0; mt < 2; mt++) {
                    #pragma unroll
                    for (int q = 0; q < 2; q++) {
                        MMA_F16(accG[mt][2 * p + q], ah[mt], bg[p][2 * q], bg[p][2 * q + 1]);
                        MMA_F16(accU[mt][2 * p + q], ah[mt], bu[p][2 * q], bu[p][2 * q + 1]);
                    }
                }
            }
        }
        __syncthreads();
    }

    // epilogue: silu(gate)*up -> fp16 act
    const int gid = lane >> 2, tig = lane & 3;
    #pragma unroll
    for (int mt = 0; mt < 2; mt++) {
        #pragma unroll
        for (int nt = 0; nt < 4; nt++) {
            int colg = n0g + wn * 32 + nt * 8 + 2 * tig;
            #pragma unroll
            for (int h = 0; h < 2; h++) {
                int rowl = wm * 32 + mt * 16 + gid + h * 8;
                if (rowl < cntm) {
                    float g0 = accG[mt][nt][2 * h],     u0 = accU[mt][nt][2 * h];
                    float g1 = accG[mt][nt][2 * h + 1], u1 = accU[mt][nt][2 * h + 1];
                    float v0 = (g0 / (1.f + __expf(-g0))) * u0;
                    float v1 = (g1 / (1.f + __expf(-g1))) * u1;
                    size_t o = (size_t)(off + m0 + rowl) * I_DIM + colg;
                    *(uint32_t*)(g_act + o) = pack_h2(__float2half_rn(v0), __float2half_rn(v1));
                }
            }
        }
    }

    // signal completion of this column tile for row block bx
    __threadfence();
    __syncthreads();
    if (tid == 0) atomicAdd(&g_flag[bx], 1);
}

// ---------------------------------------------------------------------------
// GEMM2 body (+ fused combine): out[t,:] += w * (act*Wd^T) for (bx, n0).
// Spins until all NT1 gemm1 tiles of row block bx are complete.
// ---------------------------------------------------------------------------
__device__ void gemm2_body(int bx, int n0, const float* __restrict__ wts,
                           float* __restrict__ out, char* smem_raw) {
    const int tid = threadIdx.x, lane = tid & 31, wid = tid >> 5;

    // wait for producers
    if (tid == 0) {
        volatile int* f = &g_flag[bx];
        while (*f < NT1) { }
    }
    __syncthreads();
    __threadfence();

    const int e    = g_be[bx];
    const int m0   = g_bm[bx];
    const int cnt  = g_count[e];
    const int off  = g_offset[e];
    const int cntm = cnt - m0;

    __half* smem = (__half*)smem_raw;
    const uint32_t sb = smem_u32(smem);
    const int wm = wid & 3, wn = wid >> 2;

    const __half* wb = g_wd + (size_t)e * H_DIM * I_DIM;

    auto issue = [&](int k0, int soE) {
        #pragma unroll
        for (int i = 0; i < 8; i++) {
            int idx = tid + i * 256;
            int mat = idx >> 10;
            int row = (idx >> 3) & 127;
            int seg = idx & 7;
            uint32_t dst = sb + (uint32_t)(soE + mat * TILE_E + row * STRIDE + seg * 8) * 2;
            if (mat == 0) {
                int r = (row < cntm) ? row : 0;
                const __half* src = g_act + (size_t)(off + m0 + r) * I_DIM + k0 + seg * 8;
                CP_ASYNC16(dst, src, (row < cntm) ? 16u : 0u);
            } else {
                const __half* src = wb + (size_t)(n0 + row) * I_DIM + k0 + seg * 8;
                CP_ASYNC16(dst, src, 16u);
            }
        }
        CP_COMMIT;
    };

    float acc[2][8][4];
    #pragma unroll
    for (int a = 0; a < 2; a++)
        #pragma unroll
        for (int b = 0; b < 8; b++)
            #pragma unroll
            for (int c = 0; c < 4; c++) acc[a][b][c] = 0.f;

    issue(0, 0);

    for (int c = 0; c < NCH2; c++) {
        const int s = c & 1;
        if (c + 1 < NCH2) { issue((c + 1) * KC, (s ^ 1) * STAGE_E); CP_WAIT1; }
        else CP_WAIT0;
        __syncthreads();

        const int so = s * STAGE_E;
        #pragma unroll
        for (int kk = 0; kk < KC; kk += 16) {
            uint32_t ah[2][4], bh[4][4];
            #pragma unroll
            for (int mt = 0; mt < 2; mt++)
                load_afrag(sb, so, wm * 32 + mt * 16, kk, lane, ah[mt]);
            #pragma unroll
            for (int p = 0; p < 4; p++)
                load_bfrag(sb, so + TILE_E, wn * 64 + p * 16, kk, lane, bh[p]);
            #pragma unroll
            for (int p = 0; p < 4; p++) {
                #pragma unroll
                for (int mt = 0; mt < 2; mt++) {
                    #pragma unroll
                    for (int q = 0; q < 2; q++)
                        MMA_F16(acc[mt][2 * p + q], ah[mt], bh[p][2 * q], bh[p][2 * q + 1]);
                }
            }
        }
        __syncthreads();
    }

    // fused combine epilogue
    const int gid = lane >> 2, tig = lane & 3;
    #pragma unroll
    for (int mt = 0; mt < 2; mt++) {
        #pragma unroll
        for (int h = 0; h < 2; h++) {
            int rowl = wm * 32 + mt * 16 + gid + h * 8;
            if (rowl < cntm) {
                int a = g_perm[off + m0 + rowl];
                int t = a / K_TOP;
                float w = wts[a];
                float* obase = out + (size_t)t * H_DIM;
                #pragma unroll
                for (int nt = 0; nt < 8; nt++) {
                    int col = n0 + wn * 64 + nt * 8 + 2 * tig;
                    float2 r = make_float2(w * acc[mt][nt][2 * h],
                                           w * acc[mt][nt][2 * h + 1]);
                    atomicAdd((float2*)(obase + col), r);
                }
            }
        }
    }
}

// ---------------------------------------------------------------------------
// Fused persistent GEMM kernel: ticketed work queue.
// Items [0, 12*g_nblk): gemm1, bx-major.  Then [.., +8*g_nblk): gemm2, bx-major.
// ---------------------------------------------------------------------------
__global__ __launch_bounds__(256, 2)
void moe_gemms(const float* __restrict__ wts, float* __restrict__ out) {
    extern __shared__ char smem_raw[];
    __shared__ int s_id;
    if (threadIdx.x == 0) s_id = atomicAdd(&g_ticket, 1);
    __syncthreads();
    const int id = s_id;
    const int nb = g_nblk;
    const int n1 = nb * NT1;

    if (id < n1) {
        gemm1_body(id / NT1, (id % NT1) * 64, smem_raw);
    } else {
        int j = id - n1;
        if (j >= nb * NT2) return;
        gemm2_body(j / NT2, (j % NT2) * 128, wts, out, smem_raw);
    }
}

// ---------------------------------------------------------------------------
// Launch
// ---------------------------------------------------------------------------
extern "C" void kernel_launch(void* const* d_in, const int* in_sizes, int n_in,
                              void* d_out, int out_size) {
    const float* X    = (const float*)d_in[0];
    const float* Wgu  = (const float*)d_in[1];
    const float* Wd   = (const float*)d_in[2];
    const int*   topk = (const int*)  d_in[3];
    const float* wts  = (const float*)d_in[4];
    float*       out  = (float*)d_out;

    cudaFuncSetAttribute(moe_gemms, cudaFuncAttributeMaxDynamicSharedMemorySize, SMEM_BYTES);

    prep_all<<<1025, 256>>>(X, Wgu, Wd, topk, out);
    moe_gemms<<<MAXBLK * (NT1 + NT2), 256, SMEM_BYTES>>>(wts, out);
}